// round 2
// baseline (speedup 1.0000x reference)
#include <cuda_runtime.h>

// Problem constants
#define BB 8
#define SS 1024
#define HH 1024
#define NH 16
#define HD 64
#define MM (BB*SS)   // 8192
#define KK HH        // 1024
#define NN HH        // 1024

// Scratch (no allocs allowed -> device globals)
__device__ float g_q[BB*NH*SS*HD];
__device__ float g_k[BB*NH*SS*HD];
__device__ float g_v[BB*NH*SS*HD];
__device__ float g_ctx[MM*HH];
__device__ float g_tmp[MM*HH];

// ---------------------------------------------------------------------------
// GEMM: C = A @ W^T + bias (+ residual), A [M,K] row-major, W [N,K] row-major
// MODE 0: scatter output into [B,NH,S,HD] head layout (QKV projections)
// MODE 1: plain [M,N] output + residual add (output projection)
// Tile: BM=BN=128, BK=16, 256 threads, 8x8 per thread.
// ---------------------------------------------------------------------------
template<int MODE>
__global__ __launch_bounds__(256) void gemm_nt(const float* __restrict__ A,
                                               const float* __restrict__ W,
                                               const float* __restrict__ bias,
                                               const float* __restrict__ resid,
                                               float* __restrict__ Cout)
{
    const int BM = 128, BN = 128, BK = 16;
    __shared__ float As[BK][BM];
    __shared__ float Bs[BK][BN];

    const int tid = threadIdx.x;
    const int m0 = blockIdx.y * BM;
    const int n0 = blockIdx.x * BN;
    const int tx = tid & 15;        // 0..15  (n dir)
    const int ty = tid >> 4;        // 0..15  (m dir)

    const int lrow = tid >> 2;          // 0..63
    const int lcol = (tid & 3) << 2;    // 0,4,8,12

    const float* Aptr = A + (size_t)(m0 + lrow) * KK + lcol;
    const float* Wptr = W + (size_t)(n0 + lrow) * KK + lcol;

    float acc[8][8];
#pragma unroll
    for (int i = 0; i < 8; i++)
#pragma unroll
        for (int j = 0; j < 8; j++) acc[i][j] = 0.f;

    for (int k0 = 0; k0 < KK; k0 += BK) {
        float4 a0 = *(const float4*)(Aptr + k0);
        float4 a1 = *(const float4*)(Aptr + (size_t)64 * KK + k0);
        float4 b0 = *(const float4*)(Wptr + k0);
        float4 b1 = *(const float4*)(Wptr + (size_t)64 * KK + k0);

        As[lcol+0][lrow] = a0.x; As[lcol+1][lrow] = a0.y;
        As[lcol+2][lrow] = a0.z; As[lcol+3][lrow] = a0.w;
        As[lcol+0][lrow+64] = a1.x; As[lcol+1][lrow+64] = a1.y;
        As[lcol+2][lrow+64] = a1.z; As[lcol+3][lrow+64] = a1.w;
        Bs[lcol+0][lrow] = b0.x; Bs[lcol+1][lrow] = b0.y;
        Bs[lcol+2][lrow] = b0.z; Bs[lcol+3][lrow] = b0.w;
        Bs[lcol+0][lrow+64] = b1.x; Bs[lcol+1][lrow+64] = b1.y;
        Bs[lcol+2][lrow+64] = b1.z; Bs[lcol+3][lrow+64] = b1.w;
        __syncthreads();

        const float4* As4 = reinterpret_cast<const float4*>(&As[0][0]);
        const float4* Bs4 = reinterpret_cast<const float4*>(&Bs[0][0]);
#pragma unroll
        for (int kk = 0; kk < BK; kk++) {
            float4 av0 = As4[kk*32 + ty*2 + 0];
            float4 av1 = As4[kk*32 + ty*2 + 1];
            float4 bv0 = Bs4[kk*32 + tx*2 + 0];
            float4 bv1 = Bs4[kk*32 + tx*2 + 1];
            float a[8] = {av0.x, av0.y, av0.z, av0.w, av1.x, av1.y, av1.z, av1.w};
            float b[8] = {bv0.x, bv0.y, bv0.z, bv0.w, bv1.x, bv1.y, bv1.z, bv1.w};
#pragma unroll
            for (int i = 0; i < 8; i++)
#pragma unroll
                for (int j = 0; j < 8; j++)
                    acc[i][j] = fmaf(a[i], b[j], acc[i][j]);
        }
        __syncthreads();
    }

#pragma unroll
    for (int i = 0; i < 8; i++) {
        const int m = m0 + ty * 8 + i;
        const int bidx = m >> 10;        // m / S
        const int s    = m & 1023;       // m % S
#pragma unroll
        for (int j = 0; j < 8; j++) {
            const int n = n0 + tx * 8 + j;
            float val = acc[i][j] + bias[n];
            if (MODE == 0) {
                const int h = n >> 6, d = n & 63;
                Cout[(((size_t)(bidx * NH + h)) * SS + s) * HD + d] = val;
            } else {
                Cout[(size_t)m * NN + n] = val + resid[(size_t)m * NN + n];
            }
        }
    }
}

// ---------------------------------------------------------------------------
// Flash-style attention: one block per (b, h, 64-row q tile). 256 threads.
// Thread t: row = t>>2 (0..63), quad = t&3 owns 16 cols / 16 d-channels.
// ---------------------------------------------------------------------------
#define APAD 68
#define ATTN_SMEM ((4*64*APAD + 64) * (int)sizeof(float))

__global__ __launch_bounds__(256) void attn_kernel(const float* __restrict__ q,
                                                   const float* __restrict__ k,
                                                   const float* __restrict__ v,
                                                   const float* __restrict__ mask,
                                                   float* __restrict__ ctx)
{
    extern __shared__ float sm[];
    float* Qs  = sm;                 // 64 x 68
    float* Ks  = Qs + 64 * APAD;
    float* Vs  = Ks + 64 * APAD;
    float* Ps  = Vs + 64 * APAD;
    float* Msk = Ps + 64 * APAD;     // 64

    const int tid  = threadIdx.x;
    const int qt   = blockIdx.x;     // 0..15
    const int h    = blockIdx.y;     // 0..15
    const int b_   = blockIdx.z;     // 0..7

    const float* qb = q + ((size_t)(b_ * NH + h) * SS + qt * 64) * HD;
    const float* kb = k + (size_t)(b_ * NH + h) * SS * HD;
    const float* vb = v + (size_t)(b_ * NH + h) * SS * HD;

    // Load Q tile (64x64) into padded smem
    for (int i = tid; i < 1024; i += 256) {
        const int r = i >> 4, c = (i & 15) << 2;
        *(float4*)(Qs + r * APAD + c) = *(const float4*)(qb + r * 64 + c);
    }

    const int row  = tid >> 2;
    const int quad = tid & 3;

    float m_i = -1e30f, l_i = 0.f;
    float O[16];
#pragma unroll
    for (int dd = 0; dd < 16; dd++) O[dd] = 0.f;

    for (int kt = 0; kt < 16; kt++) {
        // load K/V tiles + mask slice
        for (int i = tid; i < 1024; i += 256) {
            const int r = i >> 4, c = (i & 15) << 2;
            *(float4*)(Ks + r * APAD + c) = *(const float4*)(kb + kt * 4096 + r * 64 + c);
            *(float4*)(Vs + r * APAD + c) = *(const float4*)(vb + kt * 4096 + r * 64 + c);
        }
        if (tid < 64) Msk[tid] = mask[(size_t)b_ * SS + kt * 64 + tid];
        __syncthreads();

        // scores for my 16 columns
        float sv[16];
#pragma unroll
        for (int jj = 0; jj < 16; jj++) sv[jj] = 0.f;
#pragma unroll 4
        for (int d4 = 0; d4 < 16; d4++) {
            const float4 qv = *(const float4*)(Qs + row * APAD + d4 * 4);
#pragma unroll
            for (int jj = 0; jj < 16; jj++) {
                const float4 kv = *(const float4*)(Ks + (quad * 16 + jj) * APAD + d4 * 4);
                sv[jj] = fmaf(qv.x, kv.x, sv[jj]);
                sv[jj] = fmaf(qv.y, kv.y, sv[jj]);
                sv[jj] = fmaf(qv.z, kv.z, sv[jj]);
                sv[jj] = fmaf(qv.w, kv.w, sv[jj]);
            }
        }

        float tmax = -1e30f;
#pragma unroll
        for (int jj = 0; jj < 16; jj++) {
            sv[jj] = sv[jj] * 0.125f + Msk[quad * 16 + jj];
            tmax = fmaxf(tmax, sv[jj]);
        }
        tmax = fmaxf(tmax, __shfl_xor_sync(0xffffffffu, tmax, 1));
        tmax = fmaxf(tmax, __shfl_xor_sync(0xffffffffu, tmax, 2));

        const float m_new = fmaxf(m_i, tmax);
        const float corr  = __expf(m_i - m_new);
        float psum = 0.f;
#pragma unroll
        for (int jj = 0; jj < 16; jj++) {
            const float p = __expf(sv[jj] - m_new);
            sv[jj] = p;
            psum += p;
        }
        psum += __shfl_xor_sync(0xffffffffu, psum, 1);
        psum += __shfl_xor_sync(0xffffffffu, psum, 2);
        l_i = l_i * corr + psum;
        m_i = m_new;

#pragma unroll
        for (int jj4 = 0; jj4 < 4; jj4++)
            *(float4*)(Ps + row * APAD + quad * 16 + jj4 * 4) =
                make_float4(sv[jj4*4+0], sv[jj4*4+1], sv[jj4*4+2], sv[jj4*4+3]);
#pragma unroll
        for (int dd = 0; dd < 16; dd++) O[dd] *= corr;
        __syncthreads();

        // O += P @ V  (my 16 d-channels)
#pragma unroll 4
        for (int j = 0; j < 64; j++) {
            const float p = Ps[row * APAD + j];
            const float4 v0 = *(const float4*)(Vs + j * APAD + quad * 16 + 0);
            const float4 v1 = *(const float4*)(Vs + j * APAD + quad * 16 + 4);
            const float4 v2 = *(const float4*)(Vs + j * APAD + quad * 16 + 8);
            const float4 v3 = *(const float4*)(Vs + j * APAD + quad * 16 + 12);
            O[0]  = fmaf(p, v0.x, O[0]);  O[1]  = fmaf(p, v0.y, O[1]);
            O[2]  = fmaf(p, v0.z, O[2]);  O[3]  = fmaf(p, v0.w, O[3]);
            O[4]  = fmaf(p, v1.x, O[4]);  O[5]  = fmaf(p, v1.y, O[5]);
            O[6]  = fmaf(p, v1.z, O[6]);  O[7]  = fmaf(p, v1.w, O[7]);
            O[8]  = fmaf(p, v2.x, O[8]);  O[9]  = fmaf(p, v2.y, O[9]);
            O[10] = fmaf(p, v2.z, O[10]); O[11] = fmaf(p, v2.w, O[11]);
            O[12] = fmaf(p, v3.x, O[12]); O[13] = fmaf(p, v3.y, O[13]);
            O[14] = fmaf(p, v3.z, O[14]); O[15] = fmaf(p, v3.w, O[15]);
        }
        __syncthreads();
    }

    const float inv_l = 1.f / l_i;
    const int s_global = qt * 64 + row;
    float* outp = ctx + ((size_t)b_ * SS + s_global) * HH + h * HD + quad * 16;
    float4* op = (float4*)outp;
    op[0] = make_float4(O[0]*inv_l,  O[1]*inv_l,  O[2]*inv_l,  O[3]*inv_l);
    op[1] = make_float4(O[4]*inv_l,  O[5]*inv_l,  O[6]*inv_l,  O[7]*inv_l);
    op[2] = make_float4(O[8]*inv_l,  O[9]*inv_l,  O[10]*inv_l, O[11]*inv_l);
    op[3] = make_float4(O[12]*inv_l, O[13]*inv_l, O[14]*inv_l, O[15]*inv_l);
}

// ---------------------------------------------------------------------------
// LayerNorm over last dim (1024). One block per row, 256 threads x float4.
// ---------------------------------------------------------------------------
__global__ __launch_bounds__(256) void ln_kernel(const float* __restrict__ x,
                                                 const float* __restrict__ gamma,
                                                 const float* __restrict__ beta,
                                                 float* __restrict__ out)
{
    __shared__ float rs[8], rs2[8];
    const int r = blockIdx.x, tid = threadIdx.x;
    const float4* xr = (const float4*)(x + (size_t)r * HH);
    const float4 v = xr[tid];

    float s  = v.x + v.y + v.z + v.w;
    float s2 = v.x*v.x + v.y*v.y + v.z*v.z + v.w*v.w;
#pragma unroll
    for (int o = 16; o; o >>= 1) {
        s  += __shfl_xor_sync(0xffffffffu, s,  o);
        s2 += __shfl_xor_sync(0xffffffffu, s2, o);
    }
    if ((tid & 31) == 0) { rs[tid >> 5] = s; rs2[tid >> 5] = s2; }
    __syncthreads();
    float tot = 0.f, tot2 = 0.f;
#pragma unroll
    for (int i = 0; i < 8; i++) { tot += rs[i]; tot2 += rs2[i]; }

    const float mean = tot * (1.f / HH);
    const float var  = tot2 * (1.f / HH) - mean * mean;
    const float rstd = rsqrtf(var + 1e-12f);

    const float4 g  = ((const float4*)gamma)[tid];
    const float4 bt = ((const float4*)beta)[tid];
    float4 o;
    o.x = (v.x - mean) * rstd * g.x + bt.x;
    o.y = (v.y - mean) * rstd * g.y + bt.y;
    o.z = (v.z - mean) * rstd * g.z + bt.z;
    o.w = (v.w - mean) * rstd * g.w + bt.w;
    ((float4*)(out + (size_t)r * HH))[tid] = o;
}

// ---------------------------------------------------------------------------
extern "C" void kernel_launch(void* const* d_in, const int* in_sizes, int n_in,
                              void* d_out, int out_size)
{
    const float* hs    = (const float*)d_in[0];
    const float* mask  = (const float*)d_in[1];
    const float* Wq    = (const float*)d_in[2];
    const float* bq    = (const float*)d_in[3];
    const float* Wk    = (const float*)d_in[4];
    const float* bk    = (const float*)d_in[5];
    const float* Wv    = (const float*)d_in[6];
    const float* bv    = (const float*)d_in[7];
    const float* Wo    = (const float*)d_in[8];
    const float* bo    = (const float*)d_in[9];
    const float* gamma = (const float*)d_in[10];
    const float* beta  = (const float*)d_in[11];
    float* out = (float*)d_out;

    float *q, *k, *v, *ctx, *tmp;
    cudaGetSymbolAddress((void**)&q,   g_q);
    cudaGetSymbolAddress((void**)&k,   g_k);
    cudaGetSymbolAddress((void**)&v,   g_v);
    cudaGetSymbolAddress((void**)&ctx, g_ctx);
    cudaGetSymbolAddress((void**)&tmp, g_tmp);

    dim3 gg(NN / 128, MM / 128);   // (8, 64)

    gemm_nt<0><<<gg, 256>>>(hs, Wq, bq, nullptr, q);
    gemm_nt<0><<<gg, 256>>>(hs, Wk, bk, nullptr, k);
    gemm_nt<0><<<gg, 256>>>(hs, Wv, bv, nullptr, v);

    cudaFuncSetAttribute(attn_kernel,
                         cudaFuncAttributeMaxDynamicSharedMemorySize, ATTN_SMEM);
    attn_kernel<<<dim3(16, 16, 8), 256, ATTN_SMEM>>>(q, k, v, mask, ctx);

    gemm_nt<1><<<gg, 256>>>(ctx, Wo, bo, hs, tmp);

    ln_kernel<<<MM, 256>>>(tmp, gamma, beta, out);
}